// round 2
// baseline (speedup 1.0000x reference)
#include <cuda_runtime.h>
#include <cstdint>

#define MDd 4
#define Bn 8
#define Cn 256
#define Hn 96
#define Wn 128
#define NDISP 81
#define NEG 0.1f

typedef unsigned long long ull;

__device__ __forceinline__ void upk(ull v, float &lo, float &hi) {
    asm("mov.b64 {%0, %1}, %2;" : "=f"(lo), "=f"(hi) : "l"(v));
}
// packed fp32x2 fma: d = a*b + c elementwise on (lo,hi)
__device__ __forceinline__ ull fma2(ull a, ull b, ull c) {
    ull d;
    asm("fma.rn.f32x2 %0, %1, %2, %3;" : "=l"(d) : "l"(a), "l"(b), "l"(c));
    return d;
}
// (hi(a), lo(b)) -> the "odd" pair bridging two aligned 64-bit loads
__device__ __forceinline__ ull midpair(ull a, ull b) {
    ull r;
    asm("{\n\t"
        ".reg .b32 x,y,z,w;\n\t"
        "mov.b64 {x,y}, %1;\n\t"
        "mov.b64 {z,w}, %2;\n\t"
        "mov.b64 %0, {y,z};\n\t"
        "}" : "=l"(r) : "l"(a), "l"(b));
    return r;
}

// Block: 256 threads. tx = lane (0..31) covers w = 4*tx .. 4*tx+3 (full W row),
// ty = warp (0..7) -> output row h0+ty. Each block handles 3 dy values (dyg group).
// acc[r][dx][kp] : f32x2 over pixel pairs (4tx+2kp, 4tx+2kp+1), 54 accumulators.
__global__ __launch_bounds__(256, 1)
void corr_kernel(const float* __restrict__ x1,
                 const float* __restrict__ x2,
                 float* __restrict__ out)
{
    const int tx  = threadIdx.x & 31;
    const int ty  = threadIdx.x >> 5;
    const int h0  = blockIdx.x * 8;
    const int dyg = blockIdx.y;        // 0..2  -> dy = dyg*3 + r
    const int b   = blockIdx.z;
    const int h   = h0 + ty;

    const int wbase = 4 * tx - 4;      // x2 f[0] corresponds to global w = wbase

    // w validity for the 8 x2 LDG.64 loads (c-invariant)
    bool wv[8];
#pragma unroll
    for (int i = 0; i < 8; i++) {
        int w2 = wbase + 2 * i;
        wv[i] = (w2 >= 0) && (w2 < Wn);
    }

    // row validity + row pointers for the 3 dy values of this block (c-invariant)
    bool rv[3];
    const ull* x2p[3];
#pragma unroll
    for (int r = 0; r < 3; r++) {
        int rr = h + dyg * 3 + r - MDd;
        rv[r] = (rr >= 0) && (rr < Hn);
        int rrc = rv[r] ? rr : 0;
        x2p[r] = (const ull*)(x2 + ((size_t)b * Cn * Hn + (size_t)rrc) * Wn + wbase);
    }
    const ulonglong2* x1p =
        (const ulonglong2*)(x1 + ((size_t)b * Cn * Hn + (size_t)h) * Wn + 4 * tx);

    ull acc[3][9][2];
#pragma unroll
    for (int r = 0; r < 3; r++)
#pragma unroll
        for (int dx = 0; dx < 9; dx++) {
            acc[r][dx][0] = 0ull;
            acc[r][dx][1] = 0ull;
        }

    const int cstep_ull = (Hn * Wn) / 2;   // channel stride in 8-byte units
    const int cstep_v2  = (Hn * Wn) / 4;   // channel stride in 16-byte units

#pragma unroll 1
    for (int c = 0; c < Cn; c++) {
        // x1: 4 pixels as two aligned f32x2 pairs
        ulonglong2 a = *x1p;

#pragma unroll
        for (int r = 0; r < 3; r++) {
            if (rv[r]) {   // warp-uniform (warp == one ty)
                ull f2[8];
#pragma unroll
                for (int i = 0; i < 8; i++)
                    f2[i] = wv[i] ? x2p[r][i] : 0ull;
                ull o[5];
#pragma unroll
                for (int m = 0; m < 5; m++)
                    o[m] = midpair(f2[m], f2[m + 1]);
#pragma unroll
                for (int dx = 0; dx < 9; dx++) {
                    // pixel pair kp=0 needs pair j=dx, kp=1 needs pair j=dx+2
                    ull p0 = (dx & 1) ? o[dx >> 1] : f2[dx >> 1];
                    int j1 = dx + 2;
                    ull p1 = (j1 & 1) ? o[j1 >> 1] : f2[j1 >> 1];
                    acc[r][dx][0] = fma2(a.x, p0, acc[r][dx][0]);
                    acc[r][dx][1] = fma2(a.y, p1, acc[r][dx][1]);
                }
            }
            x2p[r] += cstep_ull;
        }
        x1p += cstep_v2;
    }

    // Epilogue: mean (1/256) + leaky relu, one STG.128 per displacement
    const float scale = 1.0f / 256.0f;
#pragma unroll
    for (int r = 0; r < 3; r++) {
#pragma unroll
        for (int dx = 0; dx < 9; dx++) {
            float v0, v1, v2, v3;
            upk(acc[r][dx][0], v0, v1);
            upk(acc[r][dx][1], v2, v3);
            v0 *= scale; v1 *= scale; v2 *= scale; v3 *= scale;
            float4 o4;
            o4.x = (v0 >= 0.0f) ? v0 : v0 * NEG;
            o4.y = (v1 >= 0.0f) ? v1 : v1 * NEG;
            o4.z = (v2 >= 0.0f) ? v2 : v2 * NEG;
            o4.w = (v3 >= 0.0f) ? v3 : v3 * NEG;
            int d = (dyg * 3 + r) * 9 + dx;
            float* op = out + (((size_t)b * NDISP + d) * Hn + h) * Wn + 4 * tx;
            *(float4*)op = o4;
        }
    }
}

extern "C" void kernel_launch(void* const* d_in, const int* in_sizes, int n_in,
                              void* d_out, int out_size)
{
    const float* x1 = (const float*)d_in[0];
    const float* x2 = (const float*)d_in[1];
    float* out = (float*)d_out;

    dim3 block(256);
    dim3 grid(Hn / 8, 3, Bn);   // (h-tiles=12, dy-groups=3, batch=8) = 288 blocks
    corr_kernel<<<grid, block>>>(x1, x2, out);
}

// round 3
// speedup vs baseline: 1.6138x; 1.6138x over previous
#include <cuda_runtime.h>
#include <cstdint>

#define MDd 4
#define Bn 8
#define Cn 256
#define Hn 96
#define Wn 128
#define NDISP 81
#define NEG 0.1f

typedef unsigned long long ull;

__device__ __forceinline__ void upk(ull v, float &lo, float &hi) {
    asm("mov.b64 {%0, %1}, %2;" : "=f"(lo), "=f"(hi) : "l"(v));
}
__device__ __forceinline__ ull pk(float lo, float hi) {
    ull r;
    asm("mov.b64 %0, {%1, %2};" : "=l"(r) : "f"(lo), "f"(hi));
    return r;
}
// packed fp32x2 fma: d = a*b + c elementwise on (lo,hi)
__device__ __forceinline__ ull fma2(ull a, ull b, ull c) {
    ull d;
    asm("fma.rn.f32x2 %0, %1, %2, %3;" : "=l"(d) : "l"(a), "l"(b), "l"(c));
    return d;
}
// (hi(a), lo(b)) -> the "odd" pair bridging two even-aligned pairs
__device__ __forceinline__ ull midpair(ull a, ull b) {
    ull r;
    asm("{\n\t"
        ".reg .b32 x,y,z,w;\n\t"
        "mov.b64 {x,y}, %1;\n\t"
        "mov.b64 {z,w}, %2;\n\t"
        "mov.b64 %0, {y,z};\n\t"
        "}" : "=l"(r) : "l"(a), "l"(b));
    return r;
}

// Block: 128 threads = 4 warps. Warp ty -> row h0+ty, lane tx -> w = 4tx..4tx+3.
// blockIdx.y = dy index (0..8), so each block accumulates 9 dx displacements
// for one dy over all 256 channels. acc[dx][kp]: f32x2 over pixel pairs.
// 36 acc regs -> 6 blocks/SM resident (24 warps, occ 37.5%).
__global__ __launch_bounds__(128, 6)
void corr_kernel(const float* __restrict__ x1,
                 const float* __restrict__ x2,
                 float* __restrict__ out)
{
    const int tx = threadIdx.x & 31;
    const int ty = threadIdx.x >> 5;
    const int h  = blockIdx.x * 4 + ty;
    const int dy = blockIdx.y;          // 0..8, row offset dy-4
    const int b  = blockIdx.z;

    ull acc[9][2];
#pragma unroll
    for (int dx = 0; dx < 9; dx++) { acc[dx][0] = 0ull; acc[dx][1] = 0ull; }

    const int rr = h + dy - MDd;
    const bool rv = (rr >= 0) && (rr < Hn);

    if (rv) {
        const int wbase = 4 * tx - 4;               // 16B-aligned float offset
        // chunk i covers w = wbase+4i .. wbase+4i+3 (4 floats, one LDG.128)
        const bool cv0 = (tx >= 1);                 // chunk0: w -4..-1 only at lane 0
        const bool cv2 = (tx <= 30);                // chunk2: w 128..131 only at lane 31

        const float4* x1p =
            (const float4*)(x1 + ((size_t)b * Cn * Hn + (size_t)h) * Wn + 4 * tx);
        const float4* x2p =
            (const float4*)(x2 + ((size_t)b * Cn * Hn + (size_t)rr) * Wn + wbase);

        const int cstep = (Hn * Wn) / 4;            // channel stride in float4
        const float4 z4 = make_float4(0.f, 0.f, 0.f, 0.f);

#pragma unroll 1
        for (int c = 0; c < Cn; c++) {
            float4 g0 = cv0 ? x2p[0] : z4;
            float4 g1 = x2p[1];
            float4 g2 = cv2 ? x2p[2] : z4;
            float4 a  = *x1p;
            x2p += cstep;
            x1p += cstep;

            ull ax = pk(a.x, a.y);
            ull ay = pk(a.z, a.w);

            // even pairs f2[0..5] over floats [wbase .. wbase+11]
            ull f2[6];
            f2[0] = pk(g0.x, g0.y); f2[1] = pk(g0.z, g0.w);
            f2[2] = pk(g1.x, g1.y); f2[3] = pk(g1.z, g1.w);
            f2[4] = pk(g2.x, g2.y); f2[5] = pk(g2.z, g2.w);
            // odd pairs o[0..4]
            ull o[5];
#pragma unroll
            for (int m = 0; m < 5; m++) o[m] = midpair(f2[m], f2[m + 1]);

#pragma unroll
            for (int dx = 0; dx < 9; dx++) {
                ull p0 = (dx & 1) ? o[dx >> 1] : f2[dx >> 1];
                int j1 = dx + 2;
                ull p1 = (j1 & 1) ? o[j1 >> 1] : f2[j1 >> 1];
                acc[dx][0] = fma2(ax, p0, acc[dx][0]);
                acc[dx][1] = fma2(ay, p1, acc[dx][1]);
            }
        }
    }

    // Epilogue: mean (1/256) + leaky relu, one STG.128 per dx
    const float scale = 1.0f / 256.0f;
#pragma unroll
    for (int dx = 0; dx < 9; dx++) {
        float v0, v1, v2, v3;
        upk(acc[dx][0], v0, v1);
        upk(acc[dx][1], v2, v3);
        v0 *= scale; v1 *= scale; v2 *= scale; v3 *= scale;
        float4 o4;
        o4.x = (v0 >= 0.0f) ? v0 : v0 * NEG;
        o4.y = (v1 >= 0.0f) ? v1 : v1 * NEG;
        o4.z = (v2 >= 0.0f) ? v2 : v2 * NEG;
        o4.w = (v3 >= 0.0f) ? v3 : v3 * NEG;
        int d = dy * 9 + dx;
        float* op = out + (((size_t)b * NDISP + d) * Hn + h) * Wn + 4 * tx;
        *(float4*)op = o4;
    }
}

extern "C" void kernel_launch(void* const* d_in, const int* in_sizes, int n_in,
                              void* d_out, int out_size)
{
    const float* x1 = (const float*)d_in[0];
    const float* x2 = (const float*)d_in[1];
    float* out = (float*)d_out;

    dim3 block(128);
    dim3 grid(Hn / 4, 9, Bn);   // (h-tiles=24, dy=9, batch=8) = 1728 blocks
    corr_kernel<<<grid, block>>>(x1, x2, out);
}